// round 15
// baseline (speedup 1.0000x reference)
#include <cuda_runtime.h>

// IntSoftmax (I-BERT) for x:(1,16,2048,2048) fp32, scaling_factor:(1,) fp32.
// One CTA of 256 threads per row of 2048; each thread owns 8 elements.
// All reference fp32 roundings replicated with explicit __f*_rn intrinsics.

#define ROW_LEN   2048
#define THREADS   256
#define F4_ROW    (ROW_LEN / 4)   // 512 float4 per row

__global__ __launch_bounds__(THREADS)
void intsoftmax_kernel(const float4* __restrict__ x4,
                       const float*  __restrict__ sfp,
                       float4* __restrict__ o4)
{
    __shared__ float s_max[8];
    __shared__ int   s_sum[8];

    const long long row = blockIdx.x;
    const float4* xr = x4 + row * (long long)F4_ROW;
    float4*       orow = o4 + row * (long long)F4_ROW;

    const int tid  = threadIdx.x;
    const int lane = tid & 31;
    const int wid  = tid >> 5;

    // ---- per-tensor derived constants (identical on every thread) ----
    const float sf     = __ldg(sfp);
    const float X0f    = (float)(-0.6931);
    const float COEF0f = (float)(0.35815147);
    const float COEF1f = (float)(0.96963238 / 0.35815147);
    const float COEF2f = (float)(1.0 / 0.35815147);

    const float x0_int = floorf(__fdiv_rn(X0f, sf));            // floor(X0/sf)
    const float b_int  = floorf(__fdiv_rn(COEF1f, sf));         // floor(COEF1/sf)
    const float sfsq   = __fmul_rn(sf, sf);
    const float c_int  = floorf(__fdiv_rn(COEF2f, sfsq));       // floor(COEF2/sf^2)
    float exp_sf = __fmul_rn(__fmul_rn(COEF0f, sf), sf);        // COEF0*sf*sf
    exp_sf = __fmul_rn(exp_sf, 0x1p-30f);                       // /2^30 (exact)
    const float clampv = __fmul_rn(30.0f, x0_int);              // CONST*x0_int
    // Global max of x_real is attained at every row's max element (x_int=0):
    //   exp_int = c_int * 2^30  ->  x_max = (c_int * 2^30) * exp_sf
    const float x_max  = __fmul_rn(__fmul_rn(c_int, 0x1p30f), exp_sf);
    const float act_sf = __fdiv_rn(x_max, 32767.0f);

    // ---- load 8 elements, divide by sf, local max ----
    float4 a = xr[tid];
    float4 b = xr[tid + THREADS];
    float v[8] = { a.x, a.y, a.z, a.w, b.x, b.y, b.z, b.w };

    float m = -__int_as_float(0x7f800000);  // -inf
    #pragma unroll
    for (int i = 0; i < 8; i++) {
        v[i] = __fdiv_rn(v[i], sf);
        m = fmaxf(m, v[i]);
    }

    // ---- block max ----
    #pragma unroll
    for (int o = 16; o > 0; o >>= 1)
        m = fmaxf(m, __shfl_xor_sync(0xffffffffu, m, o));
    if (lane == 0) s_max[wid] = m;
    __syncthreads();
    if (tid == 0) {
        float r = s_max[0];
        #pragma unroll
        for (int i = 1; i < 8; i++) r = fmaxf(r, s_max[i]);
        s_max[0] = r;
    }
    __syncthreads();
    const float rowmax = s_max[0];

    // ---- int_exp + int_polynomial + QuantAct(16), exact fp32 replication ----
    int isum = 0;
    #pragma unroll
    for (int i = 0; i < 8; i++) {
        float xi = __fsub_rn(v[i], rowmax);          // x_int - max
        xi = fmaxf(xi, clampv);                      // max(x_int, 30*x0_int)
        float q  = floorf(__fdiv_rn(xi, x0_int));    // 0..30 (may be -0.0)
        float r  = __fsub_rn(xi, __fmul_rn(x0_int, q));
        float z  = __fadd_rn(__fmul_rn(__fadd_rn(r, b_int), r), c_int);
        int   qi = (int)q;                           // (-0.0)->0, in [0,30]
        float p2 = __uint_as_float((unsigned)(157 - qi) << 23);  // 2^(30-q), exact
        float e  = fmaxf(floorf(__fmul_rn(z, p2)), 0.0f);        // exp_int
        float xr_ = __fmul_rn(e, exp_sf);            // x_real
        float qq = rintf(__fdiv_rn(xr_, act_sf));    // round half-even == jnp.round
        qq = fminf(fmaxf(qq, -32768.0f), 32767.0f);  // clip(round, -n-1, n)
        v[i] = qq;                                   // keep quantized value
        isum += (int)qq;                             // exact integer row sum
    }

    // ---- block int sum ----
    #pragma unroll
    for (int o = 16; o > 0; o >>= 1)
        isum += __shfl_xor_sync(0xffffffffu, isum, o);
    if (lane == 0) s_sum[wid] = isum;
    __syncthreads();
    if (tid == 0) {
        int r = s_sum[0];
        #pragma unroll
        for (int i = 1; i < 8; i++) r += s_sum[i];
        s_sum[0] = r;
    }
    __syncthreads();
    const float sumf   = (float)s_sum[0];            // exact if sum < 2^24 (true here)
    const float factor = floorf(__fdiv_rn(4294967296.0f, sumf)); // floor(2^32/sum)

    // ---- normalize via bit-shift + output scale ----
    #pragma unroll
    for (int i = 0; i < 8; i++) {
        float t = __fmul_rn(v[i], factor);           // single fp32 mult, same rounding
        t = floorf(__fmul_rn(t, 0x1p-24f));          // /2^24 exact, then floor
        v[i] = __fmul_rn(t, 0x1p-8f);                // * out_sf (exact)
    }

    float4 oa = { v[0], v[1], v[2], v[3] };
    float4 ob = { v[4], v[5], v[6], v[7] };
    orow[tid]           = oa;
    orow[tid + THREADS] = ob;
}

extern "C" void kernel_launch(void* const* d_in, const int* in_sizes, int n_in,
                              void* d_out, int out_size)
{
    const float* x  = (const float*)d_in[0];
    const float* sf = (const float*)d_in[1];
    float* out      = (float*)d_out;

    const int n    = in_sizes[0];
    const int rows = n / ROW_LEN;   // 32768 for (1,16,2048,2048)

    intsoftmax_kernel<<<rows, THREADS>>>(
        (const float4*)x, sf, (float4*)out);
}

// round 16
// speedup vs baseline: 1.0036x; 1.0036x over previous
#include <cuda_runtime.h>

// IntSoftmax (I-BERT) for x:(1,16,2048,2048) fp32, scaling_factor:(1,) fp32.
// One CTA of 256 threads per row of 2048; each thread owns 8 elements.
// All reference fp32 roundings replicated with explicit __f*_rn intrinsics.

#define ROW_LEN   2048
#define THREADS   256
#define F4_ROW    (ROW_LEN / 4)   // 512 float4 per row

__global__ __launch_bounds__(THREADS)
void intsoftmax_kernel(const float4* __restrict__ x4,
                       const float*  __restrict__ sfp,
                       float4* __restrict__ o4)
{
    __shared__ float s_max[8];
    __shared__ int   s_sum[8];

    const long long row = blockIdx.x;
    const float4* xr = x4 + row * (long long)F4_ROW;
    float4*       orow = o4 + row * (long long)F4_ROW;

    const int tid  = threadIdx.x;
    const int lane = tid & 31;
    const int wid  = tid >> 5;

    // ---- per-tensor derived constants (identical on every thread) ----
    const float sf     = __ldg(sfp);
    const float X0f    = (float)(-0.6931);
    const float COEF0f = (float)(0.35815147);
    const float COEF1f = (float)(0.96963238 / 0.35815147);
    const float COEF2f = (float)(1.0 / 0.35815147);

    const float x0_int = floorf(__fdiv_rn(X0f, sf));            // floor(X0/sf)
    const float b_int  = floorf(__fdiv_rn(COEF1f, sf));         // floor(COEF1/sf)
    const float sfsq   = __fmul_rn(sf, sf);
    const float c_int  = floorf(__fdiv_rn(COEF2f, sfsq));       // floor(COEF2/sf^2)
    float exp_sf = __fmul_rn(__fmul_rn(COEF0f, sf), sf);        // COEF0*sf*sf
    exp_sf = __fmul_rn(exp_sf, 0x1p-30f);                       // /2^30 (exact)
    const float clampv = __fmul_rn(30.0f, x0_int);              // CONST*x0_int
    // Global max of x_real is attained at every row's max element (x_int=0):
    //   exp_int = c_int * 2^30  ->  x_max = (c_int * 2^30) * exp_sf
    const float x_max  = __fmul_rn(__fmul_rn(c_int, 0x1p30f), exp_sf);
    const float act_sf = __fdiv_rn(x_max, 32767.0f);

    // ---- load 8 elements, divide by sf, local max ----
    float4 a = xr[tid];
    float4 b = xr[tid + THREADS];
    float v[8] = { a.x, a.y, a.z, a.w, b.x, b.y, b.z, b.w };

    float m = -__int_as_float(0x7f800000);  // -inf
    #pragma unroll
    for (int i = 0; i < 8; i++) {
        v[i] = __fdiv_rn(v[i], sf);
        m = fmaxf(m, v[i]);
    }

    // ---- block max ----
    #pragma unroll
    for (int o = 16; o > 0; o >>= 1)
        m = fmaxf(m, __shfl_xor_sync(0xffffffffu, m, o));
    if (lane == 0) s_max[wid] = m;
    __syncthreads();
    if (tid == 0) {
        float r = s_max[0];
        #pragma unroll
        for (int i = 1; i < 8; i++) r = fmaxf(r, s_max[i]);
        s_max[0] = r;
    }
    __syncthreads();
    const float rowmax = s_max[0];

    // ---- int_exp + int_polynomial + QuantAct(16), exact fp32 replication ----
    int isum = 0;
    #pragma unroll
    for (int i = 0; i < 8; i++) {
        float xi = __fsub_rn(v[i], rowmax);          // x_int - max
        xi = fmaxf(xi, clampv);                      // max(x_int, 30*x0_int)
        float q  = floorf(__fdiv_rn(xi, x0_int));    // 0..30 (may be -0.0)
        float r  = __fsub_rn(xi, __fmul_rn(x0_int, q));
        float z  = __fadd_rn(__fmul_rn(__fadd_rn(r, b_int), r), c_int);
        int   qi = (int)q;                           // (-0.0)->0, in [0,30]
        float p2 = __uint_as_float((unsigned)(157 - qi) << 23);  // 2^(30-q), exact
        float e  = fmaxf(floorf(__fmul_rn(z, p2)), 0.0f);        // exp_int
        float xr_ = __fmul_rn(e, exp_sf);            // x_real
        float qq = rintf(__fdiv_rn(xr_, act_sf));    // round half-even == jnp.round
        qq = fminf(fmaxf(qq, -32768.0f), 32767.0f);  // clip(round, -n-1, n)
        v[i] = qq;                                   // keep quantized value
        isum += (int)qq;                             // exact integer row sum
    }

    // ---- block int sum ----
    #pragma unroll
    for (int o = 16; o > 0; o >>= 1)
        isum += __shfl_xor_sync(0xffffffffu, isum, o);
    if (lane == 0) s_sum[wid] = isum;
    __syncthreads();
    if (tid == 0) {
        int r = s_sum[0];
        #pragma unroll
        for (int i = 1; i < 8; i++) r += s_sum[i];
        s_sum[0] = r;
    }
    __syncthreads();
    const float sumf   = (float)s_sum[0];            // exact if sum < 2^24 (true here)
    const float factor = floorf(__fdiv_rn(4294967296.0f, sumf)); // floor(2^32/sum)

    // ---- normalize via bit-shift + output scale ----
    #pragma unroll
    for (int i = 0; i < 8; i++) {
        float t = __fmul_rn(v[i], factor);           // single fp32 mult, same rounding
        t = floorf(__fmul_rn(t, 0x1p-24f));          // /2^24 exact, then floor
        v[i] = __fmul_rn(t, 0x1p-8f);                // * out_sf (exact)
    }

    float4 oa = { v[0], v[1], v[2], v[3] };
    float4 ob = { v[4], v[5], v[6], v[7] };
    orow[tid]           = oa;
    orow[tid + THREADS] = ob;
}

extern "C" void kernel_launch(void* const* d_in, const int* in_sizes, int n_in,
                              void* d_out, int out_size)
{
    const float* x  = (const float*)d_in[0];
    const float* sf = (const float*)d_in[1];
    float* out      = (float*)d_out;

    const int n    = in_sizes[0];
    const int rows = n / ROW_LEN;   // 32768 for (1,16,2048,2048)

    intsoftmax_kernel<<<rows, THREADS>>>(
        (const float4*)x, sf, (float4*)out);
}

// round 17
// speedup vs baseline: 1.0084x; 1.0048x over previous
#include <cuda_runtime.h>

// IntSoftmax (I-BERT) for x:(1,16,2048,2048) fp32, scaling_factor:(1,) fp32.
// One CTA of 256 threads per row of 2048; each thread owns 8 elements.
// All reference fp32 roundings replicated with explicit __f*_rn intrinsics.

#define ROW_LEN   2048
#define THREADS   256
#define F4_ROW    (ROW_LEN / 4)   // 512 float4 per row

__global__ __launch_bounds__(THREADS)
void intsoftmax_kernel(const float4* __restrict__ x4,
                       const float*  __restrict__ sfp,
                       float4* __restrict__ o4)
{
    __shared__ float s_max[8];
    __shared__ int   s_sum[8];

    const long long row = blockIdx.x;
    const float4* xr = x4 + row * (long long)F4_ROW;
    float4*       orow = o4 + row * (long long)F4_ROW;

    const int tid  = threadIdx.x;
    const int lane = tid & 31;
    const int wid  = tid >> 5;

    // ---- per-tensor derived constants (identical on every thread) ----
    const float sf     = __ldg(sfp);
    const float X0f    = (float)(-0.6931);
    const float COEF0f = (float)(0.35815147);
    const float COEF1f = (float)(0.96963238 / 0.35815147);
    const float COEF2f = (float)(1.0 / 0.35815147);

    const float x0_int = floorf(__fdiv_rn(X0f, sf));            // floor(X0/sf)
    const float b_int  = floorf(__fdiv_rn(COEF1f, sf));         // floor(COEF1/sf)
    const float sfsq   = __fmul_rn(sf, sf);
    const float c_int  = floorf(__fdiv_rn(COEF2f, sfsq));       // floor(COEF2/sf^2)
    float exp_sf = __fmul_rn(__fmul_rn(COEF0f, sf), sf);        // COEF0*sf*sf
    exp_sf = __fmul_rn(exp_sf, 0x1p-30f);                       // /2^30 (exact)
    const float clampv = __fmul_rn(30.0f, x0_int);              // CONST*x0_int
    // Global max of x_real is attained at every row's max element (x_int=0):
    //   exp_int = c_int * 2^30  ->  x_max = (c_int * 2^30) * exp_sf
    const float x_max  = __fmul_rn(__fmul_rn(c_int, 0x1p30f), exp_sf);
    const float act_sf = __fdiv_rn(x_max, 32767.0f);

    // ---- load 8 elements, divide by sf, local max ----
    float4 a = xr[tid];
    float4 b = xr[tid + THREADS];
    float v[8] = { a.x, a.y, a.z, a.w, b.x, b.y, b.z, b.w };

    float m = -__int_as_float(0x7f800000);  // -inf
    #pragma unroll
    for (int i = 0; i < 8; i++) {
        v[i] = __fdiv_rn(v[i], sf);
        m = fmaxf(m, v[i]);
    }

    // ---- block max ----
    #pragma unroll
    for (int o = 16; o > 0; o >>= 1)
        m = fmaxf(m, __shfl_xor_sync(0xffffffffu, m, o));
    if (lane == 0) s_max[wid] = m;
    __syncthreads();
    if (tid == 0) {
        float r = s_max[0];
        #pragma unroll
        for (int i = 1; i < 8; i++) r = fmaxf(r, s_max[i]);
        s_max[0] = r;
    }
    __syncthreads();
    const float rowmax = s_max[0];

    // ---- int_exp + int_polynomial + QuantAct(16), exact fp32 replication ----
    int isum = 0;
    #pragma unroll
    for (int i = 0; i < 8; i++) {
        float xi = __fsub_rn(v[i], rowmax);          // x_int - max
        xi = fmaxf(xi, clampv);                      // max(x_int, 30*x0_int)
        float q  = floorf(__fdiv_rn(xi, x0_int));    // 0..30 (may be -0.0)
        float r  = __fsub_rn(xi, __fmul_rn(x0_int, q));
        float z  = __fadd_rn(__fmul_rn(__fadd_rn(r, b_int), r), c_int);
        int   qi = (int)q;                           // (-0.0)->0, in [0,30]
        float p2 = __uint_as_float((unsigned)(157 - qi) << 23);  // 2^(30-q), exact
        float e  = fmaxf(floorf(__fmul_rn(z, p2)), 0.0f);        // exp_int
        float xr_ = __fmul_rn(e, exp_sf);            // x_real
        float qq = rintf(__fdiv_rn(xr_, act_sf));    // round half-even == jnp.round
        qq = fminf(fmaxf(qq, -32768.0f), 32767.0f);  // clip(round, -n-1, n)
        v[i] = qq;                                   // keep quantized value
        isum += (int)qq;                             // exact integer row sum
    }

    // ---- block int sum ----
    #pragma unroll
    for (int o = 16; o > 0; o >>= 1)
        isum += __shfl_xor_sync(0xffffffffu, isum, o);
    if (lane == 0) s_sum[wid] = isum;
    __syncthreads();
    if (tid == 0) {
        int r = s_sum[0];
        #pragma unroll
        for (int i = 1; i < 8; i++) r += s_sum[i];
        s_sum[0] = r;
    }
    __syncthreads();
    const float sumf   = (float)s_sum[0];            // exact if sum < 2^24 (true here)
    const float factor = floorf(__fdiv_rn(4294967296.0f, sumf)); // floor(2^32/sum)

    // ---- normalize via bit-shift + output scale ----
    #pragma unroll
    for (int i = 0; i < 8; i++) {
        float t = __fmul_rn(v[i], factor);           // single fp32 mult, same rounding
        t = floorf(__fmul_rn(t, 0x1p-24f));          // /2^24 exact, then floor
        v[i] = __fmul_rn(t, 0x1p-8f);                // * out_sf (exact)
    }

    float4 oa = { v[0], v[1], v[2], v[3] };
    float4 ob = { v[4], v[5], v[6], v[7] };
    orow[tid]           = oa;
    orow[tid + THREADS] = ob;
}

extern "C" void kernel_launch(void* const* d_in, const int* in_sizes, int n_in,
                              void* d_out, int out_size)
{
    const float* x  = (const float*)d_in[0];
    const float* sf = (const float*)d_in[1];
    float* out      = (float*)d_out;

    const int n    = in_sizes[0];
    const int rows = n / ROW_LEN;   // 32768 for (1,16,2048,2048)

    intsoftmax_kernel<<<rows, THREADS>>>(
        (const float4*)x, sf, (float4*)out);
}